// round 1
// baseline (speedup 1.0000x reference)
#include <cuda_runtime.h>
#include <math.h>

// GEBLNet: 2 generalized-eigen bilinear layers + trace head.
// Shapes: points P = 2*4096 = 8192; N_BANDS=3; U=12 output channels per layer;
// layer1: 6 input w-channels -> S1 = 13 (orig + conj-transpose + identity)
// layer2: 12 -> S2 = 25.
//
// Refactoring:
//   w_out[u] = sum_v W[v] @ C[u,v],  C[u,v] = sum_w weight[u,v,w] * W[w]
//   gerelu+trnorm -> per-channel scalar s[u] = relu(Re tr)/max(mean|tr|, 1e-3)
//
// One block per point, 160 threads, everything in shared/registers.

#define U    12
#define S1   13
#define S2   25
#define NT   160
#define MS   20          // padded float-stride per 3x3 complex matrix (18 + 2 pad, 16B aligned)
#define NPTF 180         // floats per point in x: 10 ch * 9 * 2

template<int S>
__device__ __forceinline__ void stage_c(const float* __restrict__ wgt,
                                        const float* __restrict__ sW,
                                        float* __restrict__ sC, int tid)
{
    // C[u,v]_{e} = sum_w weight[u,v,w] * W[w]_{e}   (complex, e = 0..8)
    for (int task = tid; task < U * S; task += NT) {
        float aRe[9], aIm[9];
#pragma unroll
        for (int e = 0; e < 9; e++) { aRe[e] = 0.f; aIm[e] = 0.f; }
        const float2* wrow = reinterpret_cast<const float2*>(wgt) + task * S;
        for (int w = 0; w < S; ++w) {
            float2 wv = __ldg(&wrow[w]);
            const float4* m4 = reinterpret_cast<const float4*>(sW + w * MS);
            float mv[18];
#pragma unroll
            for (int q = 0; q < 4; q++) {
                float4 f = m4[q];
                mv[4*q+0] = f.x; mv[4*q+1] = f.y; mv[4*q+2] = f.z; mv[4*q+3] = f.w;
            }
            {
                float2 f = *reinterpret_cast<const float2*>(sW + w * MS + 16);
                mv[16] = f.x; mv[17] = f.y;
            }
#pragma unroll
            for (int e = 0; e < 9; e++) {
                float br = mv[2*e], bi = mv[2*e+1];
                aRe[e] = fmaf(wv.x, br, aRe[e]);
                aRe[e] = fmaf(-wv.y, bi, aRe[e]);
                aIm[e] = fmaf(wv.x, bi, aIm[e]);
                aIm[e] = fmaf(wv.y, br, aIm[e]);
            }
        }
        float* c = sC + task * MS;
#pragma unroll
        for (int e = 0; e < 9; e++) { c[2*e] = aRe[e]; c[2*e+1] = aIm[e]; }
    }
}

template<int S>
__device__ __forceinline__ void stage_m(const float* __restrict__ sW,
                                        const float* __restrict__ sC,
                                        float* __restrict__ sM, int tid)
{
    // wout[u]_{ik} = sum_{v,j} W[v]_{ij} * C[u,v]_{jk}
    if (tid < U * 9) {
        int u = tid / 9, e = tid % 9;
        int i = e / 3, k = e % 3;
        float aRe = 0.f, aIm = 0.f;
        for (int v = 0; v < S; ++v) {
            const float* Wv = sW + v * MS + i * 6;
            const float* Cv = sC + (u * S + v) * MS + k * 2;
#pragma unroll
            for (int j = 0; j < 3; ++j) {
                float br = Wv[2*j],  bi = Wv[2*j + 1];
                float cr = Cv[j*6],  ci = Cv[j*6 + 1];
                aRe = fmaf(br, cr, aRe);
                aRe = fmaf(-bi, ci, aRe);
                aIm = fmaf(br, ci, aIm);
                aIm = fmaf(bi, cr, aIm);
            }
        }
        sM[u * MS + 2*e]     = aRe;
        sM[u * MS + 2*e + 1] = aIm;
    }
}

__global__ __launch_bounds__(NT, 8)
void gebl_kernel(const float* __restrict__ x,
                 const float* __restrict__ w1,
                 const float* __restrict__ w2,
                 const float* __restrict__ dw,
                 const float* __restrict__ db,
                 float* __restrict__ out)
{
    __shared__ float sW[S2 * MS];        // 500 floats: up to 25 matrices
    __shared__ float sC[U * S2 * MS];    // 6000 floats
    __shared__ float sM[U * MS];         // 240 floats: w_out
    __shared__ float sTrRe[U], sTrIm[U], sAbs[U], sScale[U];
    __shared__ float sNorm;

    const int tid   = threadIdx.x;
    const int point = blockIdx.x;
    const float* xp = x + (size_t)point * NPTF + 4 * 18;  // skip the 4 'u' channels

    // ---- Build W1 (6 orig + 6 conj-transpose + identity) ----
    for (int idx = tid; idx < 6 * 18; idx += NT) {
        int ch = idx / 18, r = idx % 18;
        sW[ch * MS + r] = xp[idx];
    }
    for (int idx = tid; idx < 6 * 18; idx += NT) {
        int ch = idx / 18, r = idx % 18;
        int e = r >> 1, comp = r & 1;
        int i = e / 3, j = e % 3;
        float v = xp[ch * 18 + (j * 3 + i) * 2 + comp];
        sW[(6 + ch) * MS + r] = comp ? -v : v;
    }
    if (tid < 18) {
        int e = tid >> 1, comp = tid & 1;
        sW[12 * MS + tid] = (comp == 0 && (e % 4) == 0) ? 1.0f : 0.0f;
    }
    __syncthreads();

    // ---- Layer 1 ----
    stage_c<S1>(w1, sW, sC, tid);
    __syncthreads();
    stage_m<S1>(sW, sC, sM, tid);
    __syncthreads();

    if (tid < U) {
        float trRe = sM[tid*MS + 0] + sM[tid*MS + 8] + sM[tid*MS + 16];
        float trIm = sM[tid*MS + 1] + sM[tid*MS + 9] + sM[tid*MS + 17];
        float t = fmaxf(trRe, 0.0f);
        sAbs[tid]   = t * sqrtf(trRe * trRe + trIm * trIm);
        sScale[tid] = t;
    }
    __syncthreads();
    if (tid == 0) {
        float s = 0.f;
#pragma unroll
        for (int u = 0; u < U; u++) s += sAbs[u];
        sNorm = fmaxf(s * (1.0f / U), 0.001f);
    }
    __syncthreads();
    if (tid < U) sScale[tid] = sScale[tid] / sNorm;
    __syncthreads();

    // ---- Build W2 (12 scaled + 12 scaled conj-transpose + identity) ----
    for (int idx = tid; idx < U * 18; idx += NT) {
        int ch = idx / 18, r = idx % 18;
        sW[ch * MS + r] = sM[ch * MS + r] * sScale[ch];
    }
    for (int idx = tid; idx < U * 18; idx += NT) {
        int ch = idx / 18, r = idx % 18;
        int e = r >> 1, comp = r & 1;
        int i = e / 3, j = e % 3;
        float v = sM[ch * MS + (j * 3 + i) * 2 + comp] * sScale[ch];
        sW[(U + ch) * MS + r] = comp ? -v : v;
    }
    if (tid < 18) {
        int e = tid >> 1, comp = tid & 1;
        sW[24 * MS + tid] = (comp == 0 && (e % 4) == 0) ? 1.0f : 0.0f;
    }
    __syncthreads();

    // ---- Layer 2 ----
    stage_c<S2>(w2, sW, sC, tid);
    __syncthreads();
    stage_m<S2>(sW, sC, sM, tid);
    __syncthreads();

    // ---- Layer-2 scalars + head ----
    if (tid < U) {
        float trRe = sM[tid*MS + 0] + sM[tid*MS + 8] + sM[tid*MS + 16];
        float trIm = sM[tid*MS + 1] + sM[tid*MS + 9] + sM[tid*MS + 17];
        float t = fmaxf(trRe, 0.0f);
        sTrRe[tid]  = trRe;
        sTrIm[tid]  = trIm;
        sAbs[tid]   = t * sqrtf(trRe * trRe + trIm * trIm);
        sScale[tid] = t;
    }
    __syncthreads();
    if (tid == 0) {
        float s = 0.f;
#pragma unroll
        for (int u = 0; u < U; u++) s += sAbs[u];
        float norm = fmaxf(s * (1.0f / U), 0.001f);
        float o = __ldg(&db[0]);
#pragma unroll
        for (int u = 0; u < U; u++) {
            float sc = sScale[u] / norm * (1.0f / 3.0f);
            o = fmaf(sc * sTrRe[u], __ldg(&dw[2*u]),     o);
            o = fmaf(sc * sTrIm[u], __ldg(&dw[2*u + 1]), o);
        }
        out[point] = o;
    }
}

extern "C" void kernel_launch(void* const* d_in, const int* in_sizes, int n_in,
                              void* d_out, int out_size)
{
    const float* x  = (const float*)d_in[0];
    const float* w1 = (const float*)d_in[1];
    const float* w2 = (const float*)d_in[2];
    const float* dw = (const float*)d_in[3];
    const float* db = (const float*)d_in[4];
    float* out = (float*)d_out;

    int points = in_sizes[0] / NPTF;   // 8192
    gebl_kernel<<<points, NT>>>(x, w1, w2, dw, db, out);
}

// round 2
// speedup vs baseline: 2.0408x; 2.0408x over previous
#include <cuda_runtime.h>
#include <math.h>

// GEBLNet fused kernel, round 2.
//  - weights pre-transposed to [w][u*S+v] (coalesced LDG per warp)
//  - packed fma.rn.f32x2 complex MACs with dual accumulators
//  - sC stored as [e][task] u64 (conflict-free 64-bit shared ops)

#define U    12
#define S1   13
#define S2   25
#define NT   160
#define MS   20          // padded float-stride per 3x3 complex matrix
#define NPTF 180         // floats per point: 10 ch * 9 * 2
#define T1   (U*S1)      // 156
#define T2   (U*S2)      // 300

typedef unsigned long long u64;

__device__ float g_w1T[S1 * T1 * 2];   // [w][task] complex
__device__ float g_w2T[S2 * T2 * 2];

__device__ __forceinline__ u64 pk(float lo, float hi) {
    u64 r; asm("mov.b64 %0,{%1,%2};" : "=l"(r) : "f"(lo), "f"(hi)); return r;
}
__device__ __forceinline__ void fma2(u64& d, u64 a, u64 b) {
    asm("fma.rn.f32x2 %0,%1,%2,%0;" : "+l"(d) : "l"(a), "l"(b));
}
__device__ __forceinline__ float2 up(u64 a) {
    float2 f; asm("mov.b64 {%0,%1},%2;" : "=f"(f.x), "=f"(f.y) : "l"(a)); return f;
}

__global__ void transpose_w(const float* __restrict__ w1, const float* __restrict__ w2)
{
    int tid = blockIdx.x * blockDim.x + threadIdx.x;
    if (tid < U * S1 * S1) {
        int u = tid / (S1 * S1), r = tid % (S1 * S1), v = r / S1, w = r % S1;
        int dst = w * T1 + u * S1 + v;
        g_w1T[dst * 2 + 0] = w1[tid * 2 + 0];
        g_w1T[dst * 2 + 1] = w1[tid * 2 + 1];
    }
    if (tid < U * S2 * S2) {
        int u = tid / (S2 * S2), r = tid % (S2 * S2), v = r / S2, w = r % S2;
        int dst = w * T2 + u * S2 + v;
        g_w2T[dst * 2 + 0] = w2[tid * 2 + 0];
        g_w2T[dst * 2 + 1] = w2[tid * 2 + 1];
    }
}

// C[u,v]_{e} = sum_w wgt[u,v,w] * W[w]_{e}
template<int S>
__device__ __forceinline__ void stage_c(const float* __restrict__ wT,
                                        const float* __restrict__ sW,
                                        u64* __restrict__ sC, int tid)
{
    const int T = U * S;
    for (int task = tid; task < T; task += NT) {
        u64 a1[9], a2[9];
#pragma unroll
        for (int e = 0; e < 9; e++) { a1[e] = 0ull; a2[e] = 0ull; }
        const float2* wcol = reinterpret_cast<const float2*>(wT) + task;
        for (int w = 0; w < S; ++w) {
            float2 wv = __ldg(wcol + w * T);          // coalesced across lanes
            u64 wr = pk(wv.x, wv.x), wi = pk(wv.y, wv.y);
            const float4* m4 = reinterpret_cast<const float4*>(sW + w * MS);
            float4 f0 = m4[0], f1 = m4[1], f2 = m4[2], f3 = m4[3];
            float2 ft = *reinterpret_cast<const float2*>(sW + w * MS + 16);
            u64 b[9];
            b[0] = pk(f0.x, f0.y); b[1] = pk(f0.z, f0.w);
            b[2] = pk(f1.x, f1.y); b[3] = pk(f1.z, f1.w);
            b[4] = pk(f2.x, f2.y); b[5] = pk(f2.z, f2.w);
            b[6] = pk(f3.x, f3.y); b[7] = pk(f3.z, f3.w);
            b[8] = pk(ft.x, ft.y);
#pragma unroll
            for (int e = 0; e < 9; e++) {
                fma2(a1[e], wr, b[e]);                // {wr*br, wr*bi}
                fma2(a2[e], wi, b[e]);                // {wi*br, wi*bi}
            }
        }
#pragma unroll
        for (int e = 0; e < 9; e++) {
            float2 p = up(a1[e]), q = up(a2[e]);
            sC[e * T + task] = pk(p.x - q.y, p.y + q.x);   // {re, im}
        }
    }
}

// wout[u]_{ik} = sum_{v,j} W[v]_{ij} * C[u,v]_{jk}
template<int S>
__device__ __forceinline__ void stage_m(const float* __restrict__ sW,
                                        const u64* __restrict__ sC,
                                        float* __restrict__ sM, int tid)
{
    const int T = U * S;
    if (tid < U * 9) {
        int u = tid / 9, e = tid % 9;
        int i = e / 3, k = e % 3;
        u64 a1 = 0ull, a2 = 0ull;
        for (int v = 0; v < S; ++v) {
            const float* Wv = sW + v * MS + i * 6;
            const u64*  Cv = sC + u * S + v;
#pragma unroll
            for (int j = 0; j < 3; ++j) {
                float br = Wv[2*j], bi = Wv[2*j + 1];
                u64 c = Cv[(j * 3 + k) * T];
                fma2(a1, pk(br, br), c);
                fma2(a2, pk(bi, bi), c);
            }
        }
        float2 p = up(a1), q = up(a2);
        sM[u * MS + 2*e]     = p.x - q.y;
        sM[u * MS + 2*e + 1] = p.y + q.x;
    }
}

__global__ __launch_bounds__(NT, 5)
void gebl_kernel(const float* __restrict__ x,
                 const float* __restrict__ dw,
                 const float* __restrict__ db,
                 float* __restrict__ out)
{
    __shared__ __align__(16) float sW[S2 * MS];     // 2000 B
    __shared__ u64   sC[9 * T2];                    // 21600 B
    __shared__ float sM[U * MS];                    // 960 B
    __shared__ float sTrRe[U], sTrIm[U], sAbs[U], sScale[U];

    const int tid   = threadIdx.x;
    const int point = blockIdx.x;
    const float* xp = x + (size_t)point * NPTF + 4 * 18;  // skip 'u' channels

    // ---- Build W1 (6 orig + 6 conj-transpose + identity) ----
    for (int idx = tid; idx < 6 * 18; idx += NT) {
        int ch = idx / 18, r = idx % 18;
        sW[ch * MS + r] = xp[idx];
    }
    for (int idx = tid; idx < 6 * 18; idx += NT) {
        int ch = idx / 18, r = idx % 18;
        int e = r >> 1, comp = r & 1;
        int i = e / 3, j = e % 3;
        float v = xp[ch * 18 + (j * 3 + i) * 2 + comp];
        sW[(6 + ch) * MS + r] = comp ? -v : v;
    }
    if (tid < 18) {
        int e = tid >> 1, comp = tid & 1;
        sW[12 * MS + tid] = (comp == 0 && (e % 4) == 0) ? 1.0f : 0.0f;
    }
    __syncthreads();

    // ---- Layer 1 ----
    stage_c<S1>(g_w1T, sW, sC, tid);
    __syncthreads();
    stage_m<S1>(sW, sC, sM, tid);
    __syncthreads();

    if (tid < U) {
        float trRe = sM[tid*MS + 0] + sM[tid*MS + 8] + sM[tid*MS + 16];
        float trIm = sM[tid*MS + 1] + sM[tid*MS + 9] + sM[tid*MS + 17];
        float t = fmaxf(trRe, 0.0f);
        sAbs[tid]   = t * sqrtf(trRe * trRe + trIm * trIm);
        sScale[tid] = t;
    }
    __syncthreads();
    if (tid == 0) {
        float s = 0.f;
#pragma unroll
        for (int u = 0; u < U; u++) s += sAbs[u];
        sAbs[0] = fmaxf(s * (1.0f / U), 0.001f);
    }
    __syncthreads();
    const float inv_norm1 = 1.0f / sAbs[0];
    __syncthreads();

    // ---- Build W2 (12 scaled + 12 scaled conj-transpose + identity) ----
    for (int idx = tid; idx < U * 18; idx += NT) {
        int ch = idx / 18, r = idx % 18;
        sW[ch * MS + r] = sM[ch * MS + r] * (sScale[ch] * inv_norm1);
    }
    for (int idx = tid; idx < U * 18; idx += NT) {
        int ch = idx / 18, r = idx % 18;
        int e = r >> 1, comp = r & 1;
        int i = e / 3, j = e % 3;
        float v = sM[ch * MS + (j * 3 + i) * 2 + comp] * (sScale[ch] * inv_norm1);
        sW[(U + ch) * MS + r] = comp ? -v : v;
    }
    if (tid < 18) {
        int e = tid >> 1, comp = tid & 1;
        sW[24 * MS + tid] = (comp == 0 && (e % 4) == 0) ? 1.0f : 0.0f;
    }
    __syncthreads();

    // ---- Layer 2 ----
    stage_c<S2>(g_w2T, sW, sC, tid);
    __syncthreads();
    stage_m<S2>(sW, sC, sM, tid);
    __syncthreads();

    // ---- Layer-2 scalars + head ----
    if (tid < U) {
        float trRe = sM[tid*MS + 0] + sM[tid*MS + 8] + sM[tid*MS + 16];
        float trIm = sM[tid*MS + 1] + sM[tid*MS + 9] + sM[tid*MS + 17];
        float t = fmaxf(trRe, 0.0f);
        sTrRe[tid]  = trRe;
        sTrIm[tid]  = trIm;
        sAbs[tid]   = t * sqrtf(trRe * trRe + trIm * trIm);
        sScale[tid] = t;
    }
    __syncthreads();
    if (tid == 0) {
        float s = 0.f;
#pragma unroll
        for (int u = 0; u < U; u++) s += sAbs[u];
        float norm = fmaxf(s * (1.0f / U), 0.001f);
        float o = __ldg(&db[0]);
#pragma unroll
        for (int u = 0; u < U; u++) {
            float sc = sScale[u] / norm * (1.0f / 3.0f);
            o = fmaf(sc * sTrRe[u], __ldg(&dw[2*u]),     o);
            o = fmaf(sc * sTrIm[u], __ldg(&dw[2*u + 1]), o);
        }
        out[point] = o;
    }
}

extern "C" void kernel_launch(void* const* d_in, const int* in_sizes, int n_in,
                              void* d_out, int out_size)
{
    const float* x  = (const float*)d_in[0];
    const float* w1 = (const float*)d_in[1];
    const float* w2 = (const float*)d_in[2];
    const float* dw = (const float*)d_in[3];
    const float* db = (const float*)d_in[4];
    float* out = (float*)d_out;

    int points = in_sizes[0] / NPTF;   // 8192

    transpose_w<<<(U*S2*S2 + 255) / 256, 256>>>(w1, w2);
    gebl_kernel<<<points, NT>>>(x, dw, db, out);
}